// round 9
// baseline (speedup 1.0000x reference)
#include <cuda_runtime.h>
#include <cstdint>

#define NTOK 16384
#define KEMB 8192
#define CDIM 256

#define Q_ELEMS   4194304
#define LOSS_OFF  4194304
#define PERP_OFF  4194305
#define IDX_OFF   4194306
#define SOFT_OFF  4210690ull

// ---------------- scratch (static device globals; no allocation) ----------------
__device__ float g_fn[NTOK * CDIM];        // normalized inputs  [N][C]
__device__ float g_wnT[CDIM * KEMB];       // normalized codebook, transposed [C][K]
__device__ float g_wn[KEMB * CDIM];        // normalized codebook, row-major [K][C]
__device__ float g_fn2e[NTOK];             // sum(fn^2) * log2(e)
__device__ float g_wn2[KEMB];              // sum(wn^2)
__device__ float g_wn2e[KEMB];             // sum(wn^2) * log2(e)
__device__ float g_Z[NTOK];                // softmax denominators (unnormalized exp sums)
__device__ int   g_idx[NTOK];              // argmin indices (after refine)
__device__ int   g_cand[NTOK][8];          // top-8 candidate indices per row
__device__ int   g_counts[KEMB];
__device__ float g_losspart[NTOK];

// ---------------- helpers ----------------
__device__ __forceinline__ void cpa16(float* dst, const float* src) {
    uint32_t s = (uint32_t)__cvta_generic_to_shared(dst);
    asm volatile("cp.async.cg.shared.global [%0], [%1], 16;" :: "r"(s), "l"(src));
}

// ---------------- prep: normalize codebook, store transposed + row-major ----------------
__global__ void prep_w(const float* __restrict__ emb) {
    int warp = threadIdx.x >> 5, lane = threadIdx.x & 31;
    int k = blockIdx.x * 8 + warp;
    float v[8];
#pragma unroll
    for (int j = 0; j < 8; j++) v[j] = emb[(size_t)k * CDIM + lane + 32 * j];
    float s = 0.f;
#pragma unroll
    for (int j = 0; j < 8; j++) s = fmaf(v[j], v[j], s);
#pragma unroll
    for (int o = 16; o; o >>= 1) s += __shfl_xor_sync(0xffffffffu, s, o);
    float den = fmaxf(sqrtf(s), 1e-12f);
    float t2 = 0.f;
#pragma unroll
    for (int j = 0; j < 8; j++) {
        float wn = v[j] / den;
        g_wnT[(size_t)(lane + 32 * j) * KEMB + k] = wn;
        g_wn[(size_t)k * CDIM + lane + 32 * j] = wn;
        t2 = fmaf(wn, wn, t2);
    }
#pragma unroll
    for (int o = 16; o; o >>= 1) t2 += __shfl_xor_sync(0xffffffffu, t2, o);
    if (lane == 0) { g_wn2[k] = t2; g_wn2e[k] = t2 * 1.44269504f; }
}

// ---------------- prep: normalize inputs (with NHWC gather) ----------------
__global__ void prep_x(const float* __restrict__ in) {
    int warp = threadIdx.x >> 5, lane = threadIdx.x & 31;
    int n = blockIdx.x * 8 + warp;
    int b = n >> 10, h = (n >> 5) & 31, w = n & 31;
    const float* base = in + (size_t)b * 262144 + h * 32 + w;
    float v[8];
#pragma unroll
    for (int j = 0; j < 8; j++) v[j] = base[(size_t)(lane + 32 * j) * 1024];
    float s = 0.f;
#pragma unroll
    for (int j = 0; j < 8; j++) s = fmaf(v[j], v[j], s);
#pragma unroll
    for (int o = 16; o; o >>= 1) s += __shfl_xor_sync(0xffffffffu, s, o);
    float den = fmaxf(sqrtf(s), 1e-12f);
    float t2 = 0.f;
#pragma unroll
    for (int j = 0; j < 8; j++) {
        float fn = v[j] / den;
        g_fn[(size_t)n * CDIM + lane + 32 * j] = fn;
        t2 = fmaf(fn, fn, t2);
    }
#pragma unroll
    for (int o = 16; o; o >>= 1) t2 += __shfl_xor_sync(0xffffffffu, t2, o);
    if (lane == 0) g_fn2e[n] = t2 * 1.44269504f;
}

__global__ void zero_counts() {
    int t = blockIdx.x * 256 + threadIdx.x;
    if (t < KEMB) g_counts[t] = 0;
}

// ---------------- main: fp32 GEMM + fused exp / top-2 candidates / rowsum ----------------
// CTA: 64 rows x all 8192 cols. A (64x256) resident in smem, B double-buffered.
__device__ __forceinline__ void loadB(float* Bs, int chunk, int buf, int col0, int tid) {
    const int kb = chunk * 32;
    float* dst = Bs + buf * (32 * 128);
#pragma unroll
    for (int q = 0; q < 4; q++) {
        int f = tid + 256 * q;       // 0..1023 float4s of the 32x128 tile
        int k = f >> 5;              // 32 float4 per k-row
        int c4 = (f & 31) << 2;
        cpa16(dst + k * 128 + c4, g_wnT + (size_t)(kb + k) * KEMB + col0 + c4);
    }
}

__global__ __launch_bounds__(256, 2) void vq_gemm(float* __restrict__ out) {
    extern __shared__ float smem[];
    float* As = smem;                   // [256][64] (k-major)
    float* Bs = smem + CDIM * 64;       // 2 x [32][128]
    const int tid = threadIdx.x;
    const int tc = tid & 31, tr = tid >> 5;
    const int row0 = blockIdx.x * 64;

    // Load A tile (64 rows x 256 K), transposed to k-major in smem.
    for (int j = tid; j < 64 * CDIM / 4; j += 256) {
        int r = j >> 6, c4 = (j & 63) << 2;
        float4 v = *(const float4*)(g_fn + (size_t)(row0 + r) * CDIM + c4);
        As[(c4 + 0) * 64 + r] = v.x;
        As[(c4 + 1) * 64 + r] = v.y;
        As[(c4 + 2) * 64 + r] = v.z;
        As[(c4 + 3) * 64 + r] = v.w;
    }
    float a2[8];
#pragma unroll
    for (int i = 0; i < 8; i++) a2[i] = g_fn2e[row0 + tr * 8 + i];
    float rsum[8], rmin1[8], rmin2[8]; int ridx1[8], ridx2[8];
#pragma unroll
    for (int i = 0; i < 8; i++) {
        rsum[i] = 0.f;
        rmin1[i] = 3.4e38f; ridx1[i] = 0x7fffffff;
        rmin2[i] = 3.4e38f; ridx2[i] = 0x7fffffff;
    }
    __syncthreads();

    float* soft = out + SOFT_OFF;

    for (int ct = 0; ct < KEMB / 128; ++ct) {
        const int col0 = ct * 128;
        float acc[8][4];
#pragma unroll
        for (int i = 0; i < 8; i++)
#pragma unroll
            for (int j = 0; j < 4; j++) acc[i][j] = 0.f;

        loadB(Bs, 0, 0, col0, tid);
        asm volatile("cp.async.commit_group;");
#pragma unroll
        for (int kt = 0; kt < 8; ++kt) {
            if (kt < 7) {
                loadB(Bs, kt + 1, (kt + 1) & 1, col0, tid);
                asm volatile("cp.async.commit_group;");
                asm volatile("cp.async.wait_group 1;");
            } else {
                asm volatile("cp.async.wait_group 0;");
            }
            __syncthreads();
            const float* Bc = Bs + (kt & 1) * (32 * 128);
#pragma unroll
            for (int kk = 0; kk < 32; kk++) {
                const float* ak = As + (kt * 32 + kk) * 64 + tr * 8;
                float4 A0 = *(const float4*)ak;
                float4 A1 = *(const float4*)(ak + 4);
                float4 Bv = *(const float4*)(Bc + kk * 128 + tc * 4);
                float ar[8] = {A0.x, A0.y, A0.z, A0.w, A1.x, A1.y, A1.z, A1.w};
                float br[4] = {Bv.x, Bv.y, Bv.z, Bv.w};
#pragma unroll
                for (int i = 0; i < 8; i++)
#pragma unroll
                    for (int j = 0; j < 4; j++)
                        acc[i][j] = fmaf(ar[i], br[j], acc[i][j]);
            }
            __syncthreads();
        }

        // Fused epilogue: distance proxy (top-2 per thread), exp2 softmax numerator, store.
        int cbase = col0 + tc * 4;
        float w2[4], w2e[4];
#pragma unroll
        for (int j = 0; j < 4; j++) { w2[j] = g_wn2[cbase + j]; w2e[j] = g_wn2e[cbase + j]; }
#pragma unroll
        for (int i = 0; i < 8; i++) {
            float e[4];
#pragma unroll
            for (int j = 0; j < 4; j++) {
                float dot = acc[i][j];
                float m = fmaf(dot, -2.0f, w2[j]);       // d minus row-constant fn^2
                int   mi = cbase + j;
                if (m < rmin2[i]) {
                    if (m < rmin1[i]) {
                        rmin2[i] = rmin1[i]; ridx2[i] = ridx1[i];
                        rmin1[i] = m;        ridx1[i] = mi;
                    } else {
                        rmin2[i] = m;        ridx2[i] = mi;
                    }
                }
                float t = fmaf(dot, 2.88539008f, -(a2[i] + w2e[j]));  // -d*log2e
                float ex; asm("ex2.approx.f32 %0, %1;" : "=f"(ex) : "f"(t));
                e[j] = ex;
                rsum[i] += ex;
            }
            size_t off = (size_t)(row0 + tr * 8 + i) * KEMB + cbase;
            float2* p = (float2*)(soft + off);
            p[0] = make_float2(e[0], e[1]);
            p[1] = make_float2(e[2], e[3]);
        }
    }

    // Deterministic CTA-level reduction: rowsum Z + top-8 candidate selection.
    float* redS = smem;                       // 64*32 floats
    float* redM = smem + 2048;                // 64*64 floats (two cands per thread)
    int*   redI = (int*)(smem + 2048 + 4096); // 64*64 ints
    __syncthreads();
#pragma unroll
    for (int i = 0; i < 8; i++) {
        int r = tr * 8 + i;
        redS[r * 32 + tc] = rsum[i];
        redM[r * 64 + tc * 2 + 0] = rmin1[i];
        redM[r * 64 + tc * 2 + 1] = rmin2[i];
        redI[r * 64 + tc * 2 + 0] = ridx1[i];
        redI[r * 64 + tc * 2 + 1] = ridx2[i];
    }
    __syncthreads();
    if (tid < 64) {
        int r = tid;
        float s = 0.f;
        for (int t = 0; t < 32; t++) s += redS[r * 32 + t];
        g_Z[row0 + r] = s;

        // insertion-select top-8 (by proxy value, tie-break lower index)
        float bm[8]; int bi[8];
#pragma unroll
        for (int j = 0; j < 8; j++) { bm[j] = 3.4e38f; bi[j] = 0x7fffffff; }
        for (int t = 0; t < 64; t++) {
            float m = redM[r * 64 + t]; int iv = redI[r * 64 + t];
            if (m < bm[7] || (m == bm[7] && iv < bi[7])) {
                int j = 7;
                while (j > 0 && (m < bm[j - 1] || (m == bm[j - 1] && iv < bi[j - 1]))) {
                    bm[j] = bm[j - 1]; bi[j] = bi[j - 1]; --j;
                }
                bm[j] = m; bi[j] = iv;
            }
        }
#pragma unroll
        for (int j = 0; j < 8; j++) g_cand[row0 + r][j] = bi[j];
    }
}

// ---------------- argmin refine: exact (double) distance over top-8 candidates ----------------
// warp per row; lane = cand*4 + part; each part covers 64 of 256 dims.
__global__ void refine_k() {
    int warp = threadIdx.x >> 5, lane = threadIdx.x & 31;
    int n = blockIdx.x * 8 + warp;
    int cand = lane >> 2, part = lane & 3;
    int k = g_cand[n][cand];
    const float* fnr = g_fn + (size_t)n * CDIM;
    const float* wr  = g_wn + (size_t)k * CDIM;
    double dot = 0.0, w2 = 0.0;
    int c0 = part * 64;
#pragma unroll 8
    for (int c = c0; c < c0 + 64; c++) {
        double w = (double)wr[c];
        dot = fma((double)fnr[c], w, dot);
        w2  = fma(w, w, w2);
    }
    // reduce the 4 parts of each candidate
#pragma unroll
    for (int o = 1; o < 4; o <<= 1) {
        dot += __shfl_xor_sync(0xffffffffu, dot, o);
        w2  += __shfl_xor_sync(0xffffffffu, w2,  o);
    }
    double d = w2 - 2.0 * dot;   // fn^2 row-constant omitted (same for all candidates)
    // min-reduce across the 8 candidates, tie-break lower index
#pragma unroll
    for (int o = 4; o < 32; o <<= 1) {
        double od = __shfl_xor_sync(0xffffffffu, d, o);
        int    ok = __shfl_xor_sync(0xffffffffu, k, o);
        if (od < d || (od == d && ok < k)) { d = od; k = ok; }
    }
    if (lane == 0) g_idx[n] = k;
}

// ---------------- scale soft codes by 1/Z (inv fused; deterministic per row) ----------------
__global__ void scale_soft(float* __restrict__ out) {
    float2* soft = (float2*)(out + SOFT_OFF);
    size_t base = (size_t)blockIdx.x * 256 + threadIdx.x;
#pragma unroll
    for (int q = 0; q < 4; q++) {
        size_t i = base + (size_t)q * 16777216u;   // 65536*256
        int n = (int)(i >> 12);                    // 4096 float2 per row
        float inv = 1.0f / g_Z[n];
        float2 v = soft[i];
        v.x *= inv; v.y *= inv;
        soft[i] = v;
    }
}

// ---------------- gather quantized, loss partials, counts, indices ----------------
__global__ void quantize_k(const float* __restrict__ in, const float* __restrict__ emb,
                           float* __restrict__ out) {
    int warp = threadIdx.x >> 5, lane = threadIdx.x & 31;
    int n = blockIdx.x * 8 + warp;
    int idx = g_idx[n];
    int b = n >> 10, h = (n >> 5) & 31, w = n & 31;
    const float* er = emb + (size_t)idx * CDIM;
    const float* xb = in + (size_t)b * 262144 + h * 32 + w;
    float* ob = out + (size_t)b * 262144 + w * 32 + h;   // [B,C,W,H] layout
    float ls = 0.f;
#pragma unroll
    for (int j = 0; j < 8; j++) {
        int c = lane + 32 * j;
        float q = er[c];
        float x = xb[(size_t)c * 1024];
        float d = q - x;
        ls = fmaf(d, d, ls);
        ob[(size_t)c * 1024] = q;
    }
#pragma unroll
    for (int o = 16; o; o >>= 1) ls += __shfl_xor_sync(0xffffffffu, ls, o);
    if (lane == 0) {
        g_losspart[n] = ls;
        atomicAdd(&g_counts[idx], 1);
        out[IDX_OFF + n] = (float)idx;
    }
}

// ---------------- final scalars ----------------
__global__ void finalize_k(float* __restrict__ out) {
    __shared__ float sred[1024];
    int tid = threadIdx.x;
    float s = 0.f;
    for (int i = 0; i < 16; i++) s += g_losspart[tid + 1024 * i];
    sred[tid] = s; __syncthreads();
    for (int o = 512; o; o >>= 1) { if (tid < o) sred[tid] += sred[tid + o]; __syncthreads(); }
    if (tid == 0) out[LOSS_OFF] = 0.25f * (sred[0] * (1.0f / 4194304.0f));
    __syncthreads();
    float e = 0.f;
    for (int i = 0; i < 8; i++) {
        float p = (float)g_counts[tid + 1024 * i] * (1.0f / 16384.0f);
        e += p * logf(p + 1e-10f);
    }
    sred[tid] = e; __syncthreads();
    for (int o = 512; o; o >>= 1) { if (tid < o) sred[tid] += sred[tid + o]; __syncthreads(); }
    if (tid == 0) out[PERP_OFF] = expf(-sred[0]);
}

// ---------------- launcher ----------------
extern "C" void kernel_launch(void* const* d_in, const int* in_sizes, int n_in,
                              void* d_out, int out_size) {
    (void)in_sizes; (void)n_in; (void)out_size;
    const float* in  = (const float*)d_in[0];
    const float* emb = (const float*)d_in[1];
    float* out = (float*)d_out;

    cudaFuncSetAttribute(vq_gemm, cudaFuncAttributeMaxDynamicSharedMemorySize, 98304);

    prep_w<<<KEMB / 8, 256>>>(emb);
    prep_x<<<NTOK / 8, 256>>>(in);
    zero_counts<<<32, 256>>>();
    vq_gemm<<<NTOK / 64, 256, 98304>>>(out);
    refine_k<<<NTOK / 8, 256>>>();
    scale_soft<<<65536, 256>>>(out);
    quantize_k<<<NTOK / 8, 256>>>(in, emb, out);
    finalize_k<<<1, 1024>>>(out);
}

// round 11
// speedup vs baseline: 1.1247x; 1.1247x over previous
#include <cuda_runtime.h>
#include <cstdint>

#define NTOK 16384
#define KEMB 8192
#define CDIM 256

#define Q_ELEMS   4194304
#define LOSS_OFF  4194304
#define PERP_OFF  4194305
#define IDX_OFF   4194306
#define SOFT_OFF  4210690ull

typedef unsigned long long u64;

// ---------------- scratch (static device globals; no allocation) ----------------
__device__ float g_fn[NTOK * CDIM];        // normalized inputs  [N][C]
__device__ float g_wnT[CDIM * KEMB];       // normalized codebook, transposed [C][K]
__device__ float g_wn[KEMB * CDIM];        // normalized codebook, row-major [K][C]
__device__ float g_fn2e[NTOK];             // sum(fn^2) * log2(e)
__device__ float g_wn2[KEMB];              // sum(wn^2)
__device__ float g_wn2e[KEMB];             // sum(wn^2) * log2(e)
__device__ float g_Z[NTOK];                // softmax denominators
__device__ int   g_idx[NTOK];              // argmin indices (after refine)
__device__ int   g_cand[NTOK][8];          // top-8 candidate indices per row
__device__ int   g_counts[KEMB];
__device__ float g_losspart[NTOK];

// ---------------- helpers ----------------
__device__ __forceinline__ void cpa16(float* dst, const float* src) {
    uint32_t s = (uint32_t)__cvta_generic_to_shared(dst);
    asm volatile("cp.async.cg.shared.global [%0], [%1], 16;" :: "r"(s), "l"(src));
}

#define PACKDUP(d, s)    asm("mov.b64 %0, {%1, %1};" : "=l"(d) : "f"(s))
#define UNPACK2(lo, hi, s) asm("mov.b64 {%0, %1}, %2;" : "=f"(lo), "=f"(hi) : "l"(s))
#define FMA2(acc, a, b)  asm("fma.rn.f32x2 %0, %1, %2, %0;" : "+l"(acc) : "l"(a), "l"(b))

// ---------------- prep: normalize codebook, store transposed + row-major ----------------
__global__ void prep_w(const float* __restrict__ emb) {
    int warp = threadIdx.x >> 5, lane = threadIdx.x & 31;
    int k = blockIdx.x * 8 + warp;
    float v[8];
#pragma unroll
    for (int j = 0; j < 8; j++) v[j] = emb[(size_t)k * CDIM + lane + 32 * j];
    float s = 0.f;
#pragma unroll
    for (int j = 0; j < 8; j++) s = fmaf(v[j], v[j], s);
#pragma unroll
    for (int o = 16; o; o >>= 1) s += __shfl_xor_sync(0xffffffffu, s, o);
    float den = fmaxf(sqrtf(s), 1e-12f);
    float t2 = 0.f;
#pragma unroll
    for (int j = 0; j < 8; j++) {
        float wn = v[j] / den;
        g_wnT[(size_t)(lane + 32 * j) * KEMB + k] = wn;
        g_wn[(size_t)k * CDIM + lane + 32 * j] = wn;
        t2 = fmaf(wn, wn, t2);
    }
#pragma unroll
    for (int o = 16; o; o >>= 1) t2 += __shfl_xor_sync(0xffffffffu, t2, o);
    if (lane == 0) { g_wn2[k] = t2; g_wn2e[k] = t2 * 1.44269504f; }
}

// ---------------- prep: normalize inputs (with NHWC gather) ----------------
__global__ void prep_x(const float* __restrict__ in) {
    int warp = threadIdx.x >> 5, lane = threadIdx.x & 31;
    int n = blockIdx.x * 8 + warp;
    int b = n >> 10, h = (n >> 5) & 31, w = n & 31;
    const float* base = in + (size_t)b * 262144 + h * 32 + w;
    float v[8];
#pragma unroll
    for (int j = 0; j < 8; j++) v[j] = base[(size_t)(lane + 32 * j) * 1024];
    float s = 0.f;
#pragma unroll
    for (int j = 0; j < 8; j++) s = fmaf(v[j], v[j], s);
#pragma unroll
    for (int o = 16; o; o >>= 1) s += __shfl_xor_sync(0xffffffffu, s, o);
    float den = fmaxf(sqrtf(s), 1e-12f);
    float t2 = 0.f;
#pragma unroll
    for (int j = 0; j < 8; j++) {
        float fn = v[j] / den;
        g_fn[(size_t)n * CDIM + lane + 32 * j] = fn;
        t2 = fmaf(fn, fn, t2);
    }
#pragma unroll
    for (int o = 16; o; o >>= 1) t2 += __shfl_xor_sync(0xffffffffu, t2, o);
    if (lane == 0) g_fn2e[n] = t2 * 1.44269504f;
}

__global__ void zero_counts() {
    int t = blockIdx.x * 256 + threadIdx.x;
    if (t < KEMB) g_counts[t] = 0;
}

// ---------------- main: packed-f32x2 GEMM + fused exp / top-2 candidates / rowsum -------
// CTA: 128 rows x all 8192 cols (32 col-tiles of 256). A resident (128KB, k-major),
// B double-buffered 32k x 256c slabs via cp.async. Thread tile 8 rows x 8 cols (FFMA2).
__device__ __forceinline__ void loadB(float* Bs, int chunk, int buf, int col0, int tid) {
    const int kb = chunk * 32;
    float* dst = Bs + buf * (32 * 256);
#pragma unroll
    for (int q = 0; q < 4; q++) {
        int f = tid + 512 * q;       // 0..2047 float4s of the 32x256 tile
        int k = f >> 6;              // 64 float4 per k-row
        int c4 = (f & 63) << 2;
        cpa16(dst + k * 256 + c4, g_wnT + (size_t)(kb + k) * KEMB + col0 + c4);
    }
}

__global__ __launch_bounds__(512, 1) void vq_gemm(float* __restrict__ out) {
    extern __shared__ float smem[];
    float* As = smem;                    // [256][128] k-major: As[k*128 + r]
    float* Bs = smem + CDIM * 128;       // 2 x [32][256]
    const int tid = threadIdx.x;
    const int tc = tid & 31, tr = tid >> 5;   // tr 0..15 (row group), tc 0..31 (col group)
    const int row0 = blockIdx.x * 128;

    // Load A tile (128 rows x 256 K), transposed to k-major in smem.
    for (int j = tid; j < 128 * CDIM / 4; j += 512) {
        int r = j >> 6, c4 = (j & 63) << 2;
        float4 v = *(const float4*)(g_fn + (size_t)(row0 + r) * CDIM + c4);
        As[(c4 + 0) * 128 + r] = v.x;
        As[(c4 + 1) * 128 + r] = v.y;
        As[(c4 + 2) * 128 + r] = v.z;
        As[(c4 + 3) * 128 + r] = v.w;
    }
    float a2[8];
#pragma unroll
    for (int i = 0; i < 8; i++) a2[i] = g_fn2e[row0 + tr * 8 + i];
    float rsum[8], rmin1[8], rmin2[8]; int ridx1[8], ridx2[8];
#pragma unroll
    for (int i = 0; i < 8; i++) {
        rsum[i] = 0.f;
        rmin1[i] = 3.4e38f; ridx1[i] = 0x7fffffff;
        rmin2[i] = 3.4e38f; ridx2[i] = 0x7fffffff;
    }
    __syncthreads();

    float* soft = out + SOFT_OFF;

    for (int ct = 0; ct < KEMB / 256; ++ct) {
        const int col0 = ct * 256;
        u64 acc[8][4];                  // 8 rows x 4 col-pairs (8 cols), packed f32x2
#pragma unroll
        for (int i = 0; i < 8; i++)
#pragma unroll
            for (int j = 0; j < 4; j++) acc[i][j] = 0ull;

        loadB(Bs, 0, 0, col0, tid);
        asm volatile("cp.async.commit_group;");
        for (int kt = 0; kt < 8; ++kt) {
            if (kt < 7) {
                loadB(Bs, kt + 1, (kt + 1) & 1, col0, tid);
                asm volatile("cp.async.commit_group;");
                asm volatile("cp.async.wait_group 1;");
            } else {
                asm volatile("cp.async.wait_group 0;");
            }
            __syncthreads();
            const float* Bc = Bs + (kt & 1) * (32 * 256);
#pragma unroll 8
            for (int kk = 0; kk < 32; kk++) {
                const float* ak = As + (kt * 32 + kk) * 128 + tr * 8;
                float4 A0 = *(const float4*)ak;            // broadcast within warp
                float4 A1 = *(const float4*)(ak + 4);
                u64 ad[8];
                PACKDUP(ad[0], A0.x); PACKDUP(ad[1], A0.y);
                PACKDUP(ad[2], A0.z); PACKDUP(ad[3], A0.w);
                PACKDUP(ad[4], A1.x); PACKDUP(ad[5], A1.y);
                PACKDUP(ad[6], A1.z); PACKDUP(ad[7], A1.w);
                const u64* bp = (const u64*)(Bc + kk * 256 + tc * 8);
                u64 b0 = bp[0], b1 = bp[1], b2 = bp[2], b3 = bp[3];
#pragma unroll
                for (int i = 0; i < 8; i++) {
                    FMA2(acc[i][0], ad[i], b0);
                    FMA2(acc[i][1], ad[i], b1);
                    FMA2(acc[i][2], ad[i], b2);
                    FMA2(acc[i][3], ad[i], b3);
                }
            }
            __syncthreads();
        }

        // Fused epilogue: distance proxy (top-2 per thread), exp2 numerator, store.
        // NOTE: soft base is only 8-byte aligned (SOFT_OFF % 4 == 2) -> float2 stores only.
        int cbase = col0 + tc * 8;
        float w2[8], w2e[8];
#pragma unroll
        for (int j = 0; j < 8; j++) { w2[j] = g_wn2[cbase + j]; w2e[j] = g_wn2e[cbase + j]; }
#pragma unroll
        for (int i = 0; i < 8; i++) {
            float e[8];
#pragma unroll
            for (int j = 0; j < 4; j++) {
                float d0, d1;
                UNPACK2(d0, d1, acc[i][j]);
                float dots[2] = {d0, d1};
#pragma unroll
                for (int h = 0; h < 2; h++) {
                    int jc = j * 2 + h;
                    float dot = dots[h];
                    float m = fmaf(dot, -2.0f, w2[jc]);   // d minus row-constant fn^2
                    int   mi = cbase + jc;
                    if (m < rmin2[i]) {
                        if (m < rmin1[i]) {
                            rmin2[i] = rmin1[i]; ridx2[i] = ridx1[i];
                            rmin1[i] = m;        ridx1[i] = mi;
                        } else {
                            rmin2[i] = m;        ridx2[i] = mi;
                        }
                    }
                    float t = fmaf(dot, 2.88539008f, -(a2[i] + w2e[jc]));  // -d*log2e
                    float ex; asm("ex2.approx.f32 %0, %1;" : "=f"(ex) : "f"(t));
                    e[jc] = ex;
                    rsum[i] += ex;
                }
            }
            size_t off = (size_t)(row0 + tr * 8 + i) * KEMB + cbase;
            float2* p = (float2*)(soft + off);
            p[0] = make_float2(e[0], e[1]);
            p[1] = make_float2(e[2], e[3]);
            p[2] = make_float2(e[4], e[5]);
            p[3] = make_float2(e[6], e[7]);
        }
    }

    // Deterministic CTA-level reduction: rowsum Z + top-8 candidate selection.
    float* redS = smem;                        // 128*32 floats (16KB)
    float* redM = smem + 4096;                 // 128*64 floats (32KB)
    int*   redI = (int*)(smem + 4096 + 8192);  // 128*64 ints  (32KB)
    __syncthreads();
#pragma unroll
    for (int i = 0; i < 8; i++) {
        int r = tr * 8 + i;
        redS[r * 32 + tc] = rsum[i];
        redM[r * 64 + tc * 2 + 0] = rmin1[i];
        redM[r * 64 + tc * 2 + 1] = rmin2[i];
        redI[r * 64 + tc * 2 + 0] = ridx1[i];
        redI[r * 64 + tc * 2 + 1] = ridx2[i];
    }
    __syncthreads();
    if (tid < 128) {
        int r = tid;
        float s = 0.f;
        for (int t = 0; t < 32; t++) s += redS[r * 32 + t];
        g_Z[row0 + r] = s;

        // insertion-select top-8 (by proxy value, tie-break lower index)
        float bm[8]; int bi[8];
#pragma unroll
        for (int j = 0; j < 8; j++) { bm[j] = 3.4e38f; bi[j] = 0x7fffffff; }
        for (int t = 0; t < 64; t++) {
            float m = redM[r * 64 + t]; int iv = redI[r * 64 + t];
            if (m < bm[7] || (m == bm[7] && iv < bi[7])) {
                int j = 7;
                while (j > 0 && (m < bm[j - 1] || (m == bm[j - 1] && iv < bi[j - 1]))) {
                    bm[j] = bm[j - 1]; bi[j] = bi[j - 1]; --j;
                }
                bm[j] = m; bi[j] = iv;
            }
        }
#pragma unroll
        for (int j = 0; j < 8; j++) g_cand[row0 + r][j] = bi[j];
    }
}

// ---------------- argmin refine: exact (double) distance over top-8 candidates ----------------
__global__ void refine_k() {
    int warp = threadIdx.x >> 5, lane = threadIdx.x & 31;
    int n = blockIdx.x * 8 + warp;
    int cand = lane >> 2, part = lane & 3;
    int k = g_cand[n][cand];
    const float* fnr = g_fn + (size_t)n * CDIM;
    const float* wr  = g_wn + (size_t)k * CDIM;
    double dot = 0.0, w2 = 0.0;
    int c0 = part * 64;
#pragma unroll 8
    for (int c = c0; c < c0 + 64; c++) {
        double w = (double)wr[c];
        dot = fma((double)fnr[c], w, dot);
        w2  = fma(w, w, w2);
    }
#pragma unroll
    for (int o = 1; o < 4; o <<= 1) {
        dot += __shfl_xor_sync(0xffffffffu, dot, o);
        w2  += __shfl_xor_sync(0xffffffffu, w2,  o);
    }
    double d = w2 - 2.0 * dot;   // fn^2 row-constant omitted (same for all candidates)
#pragma unroll
    for (int o = 4; o < 32; o <<= 1) {
        double od = __shfl_xor_sync(0xffffffffu, d, o);
        int    ok = __shfl_xor_sync(0xffffffffu, k, o);
        if (od < d || (od == d && ok < k)) { d = od; k = ok; }
    }
    if (lane == 0) g_idx[n] = k;
}

// ---------------- scale soft codes by 1/Z ----------------
__global__ void scale_soft(float* __restrict__ out) {
    float2* soft = (float2*)(out + SOFT_OFF);
    size_t base = (size_t)blockIdx.x * 256 + threadIdx.x;
#pragma unroll
    for (int q = 0; q < 4; q++) {
        size_t i = base + (size_t)q * 16777216u;   // 65536*256
        int n = (int)(i >> 12);                    // 4096 float2 per row
        float inv = 1.0f / g_Z[n];
        float2 v = soft[i];
        v.x *= inv; v.y *= inv;
        soft[i] = v;
    }
}

// ---------------- gather quantized, loss partials, counts, indices ----------------
__global__ void quantize_k(const float* __restrict__ in, const float* __restrict__ emb,
                           float* __restrict__ out) {
    int warp = threadIdx.x >> 5, lane = threadIdx.x & 31;
    int n = blockIdx.x * 8 + warp;
    int idx = g_idx[n];
    int b = n >> 10, h = (n >> 5) & 31, w = n & 31;
    const float* er = emb + (size_t)idx * CDIM;
    const float* xb = in + (size_t)b * 262144 + h * 32 + w;
    float* ob = out + (size_t)b * 262144 + w * 32 + h;   // [B,C,W,H] layout
    float ls = 0.f;
#pragma unroll
    for (int j = 0; j < 8; j++) {
        int c = lane + 32 * j;
        float q = er[c];
        float x = xb[(size_t)c * 1024];
        float d = q - x;
        ls = fmaf(d, d, ls);
        ob[(size_t)c * 1024] = q;
    }
#pragma unroll
    for (int o = 16; o; o >>= 1) ls += __shfl_xor_sync(0xffffffffu, ls, o);
    if (lane == 0) {
        g_losspart[n] = ls;
        atomicAdd(&g_counts[idx], 1);
        out[IDX_OFF + n] = (float)idx;
    }
}

// ---------------- final scalars ----------------
__global__ void finalize_k(float* __restrict__ out) {
    __shared__ float sred[1024];
    int tid = threadIdx.x;
    float s = 0.f;
    for (int i = 0; i < 16; i++) s += g_losspart[tid + 1024 * i];
    sred[tid] = s; __syncthreads();
    for (int o = 512; o; o >>= 1) { if (tid < o) sred[tid] += sred[tid + o]; __syncthreads(); }
    if (tid == 0) out[LOSS_OFF] = 0.25f * (sred[0] * (1.0f / 4194304.0f));
    __syncthreads();
    float e = 0.f;
    for (int i = 0; i < 8; i++) {
        float p = (float)g_counts[tid + 1024 * i] * (1.0f / 16384.0f);
        e += p * logf(p + 1e-10f);
    }
    sred[tid] = e; __syncthreads();
    for (int o = 512; o; o >>= 1) { if (tid < o) sred[tid] += sred[tid + o]; __syncthreads(); }
    if (tid == 0) out[PERP_OFF] = expf(-sred[0]);
}

// ---------------- launcher ----------------
extern "C" void kernel_launch(void* const* d_in, const int* in_sizes, int n_in,
                              void* d_out, int out_size) {
    (void)in_sizes; (void)n_in; (void)out_size;
    const float* in  = (const float*)d_in[0];
    const float* emb = (const float*)d_in[1];
    float* out = (float*)d_out;

    // A resident 128KB + B double-buffer 64KB = 192KB dynamic smem
    cudaFuncSetAttribute(vq_gemm, cudaFuncAttributeMaxDynamicSharedMemorySize, 196608);

    prep_w<<<KEMB / 8, 256>>>(emb);
    prep_x<<<NTOK / 8, 256>>>(in);
    zero_counts<<<32, 256>>>();
    vq_gemm<<<NTOK / 128, 512, 196608>>>(out);
    refine_k<<<NTOK / 8, 256>>>();
    scale_soft<<<65536, 256>>>(out);
    quantize_k<<<NTOK / 8, 256>>>(in, emb, out);
    finalize_k<<<1, 1024>>>(out);
}

// round 14
// speedup vs baseline: 2.3677x; 2.1052x over previous
#include <cuda_runtime.h>
#include <cuda_bf16.h>
#include <cstdint>

#define NTOK 16384
#define KEMB 8192
#define CDIM 256

#define LOSS_OFF  4194304
#define PERP_OFF  4194305
#define IDX_OFF   4194306
#define SOFT_OFF  4210690ull

#define NT 256                 // 8192 cols / 32 per tile
#define BPAD 264               // padded bf16 per B row (528 B)
#define BUF_ELEMS (2 * 32 * BPAD)   // hi block + lo block, bf16 units (33792 B)

// ---------------- scratch (static device globals; no allocation) ----------------
__device__ float         g_fn[NTOK * CDIM];       // normalized inputs  [N][C] fp32
__device__ __nv_bfloat16 g_whk[KEMB * CDIM];      // codebook normalized, bf16 hi [K][C]
__device__ __nv_bfloat16 g_wlk[KEMB * CDIM];      // codebook normalized, bf16 lo [K][C]
__device__ float         g_wn[KEMB * CDIM];       // codebook normalized fp32 (refine)
__device__ float g_fn2e[NTOK];
__device__ float g_wn2[KEMB];
__device__ float g_wn2e[KEMB];
__device__ float g_Z[NTOK];
__device__ int   g_idx[NTOK];
__device__ int   g_cand[NTOK][4];
__device__ int   g_counts[KEMB];
__device__ float g_losspart[NTOK];

// ---------------- helpers ----------------
__device__ __forceinline__ void cpa16_s(void* dst, const void* src) {
    uint32_t s;
    asm("{ .reg .u64 t; cvta.to.shared.u64 t, %1; cvt.u32.u64 %0, t; }" : "=r"(s) : "l"(dst));
    asm volatile("cp.async.cg.shared.global [%0], [%1], 16;" :: "r"(s), "l"(src));
}

__device__ __forceinline__ void mma_bf16(float* d, const uint32_t* a, const uint32_t* b) {
    asm volatile(
        "mma.sync.aligned.m16n8k16.row.col.f32.bf16.bf16.f32 "
        "{%0,%1,%2,%3}, {%4,%5,%6,%7}, {%8,%9}, {%0,%1,%2,%3};"
        : "+f"(d[0]), "+f"(d[1]), "+f"(d[2]), "+f"(d[3])
        : "r"(a[0]), "r"(a[1]), "r"(a[2]), "r"(a[3]), "r"(b[0]), "r"(b[1]));
}

__device__ __forceinline__ void packhl(float x0, float x1, uint32_t& h, uint32_t& l) {
    __nv_bfloat16 h0 = __float2bfloat16(x0), h1 = __float2bfloat16(x1);
    h = ((uint32_t)__bfloat16_as_ushort(h1) << 16) | __bfloat16_as_ushort(h0);
    float l0 = x0 - __bfloat162float(h0), l1 = x1 - __bfloat162float(h1);
    __nv_bfloat16 b0 = __float2bfloat16(l0), b1 = __float2bfloat16(l1);
    l = ((uint32_t)__bfloat16_as_ushort(b1) << 16) | __bfloat16_as_ushort(b0);
}

// ---------------- prep: normalize codebook -> bf16 hi/lo [K][C] + fp32 ----------------
__global__ void prep_w(const float* __restrict__ emb) {
    int warp = threadIdx.x >> 5, lane = threadIdx.x & 31;
    int k = blockIdx.x * 8 + warp;
    float v[8];
#pragma unroll
    for (int j = 0; j < 8; j++) v[j] = emb[(size_t)k * CDIM + lane + 32 * j];
    float s = 0.f;
#pragma unroll
    for (int j = 0; j < 8; j++) s = fmaf(v[j], v[j], s);
#pragma unroll
    for (int o = 16; o; o >>= 1) s += __shfl_xor_sync(0xffffffffu, s, o);
    float den = fmaxf(sqrtf(s), 1e-12f);
    float t2 = 0.f;
#pragma unroll
    for (int j = 0; j < 8; j++) {
        float wn = v[j] / den;
        int c = lane + 32 * j;
        g_wn[(size_t)k * CDIM + c] = wn;
        __nv_bfloat16 h = __float2bfloat16(wn);
        g_whk[(size_t)k * CDIM + c] = h;
        g_wlk[(size_t)k * CDIM + c] = __float2bfloat16(wn - __bfloat162float(h));
        t2 = fmaf(wn, wn, t2);
    }
#pragma unroll
    for (int o = 16; o; o >>= 1) t2 += __shfl_xor_sync(0xffffffffu, t2, o);
    if (lane == 0) { g_wn2[k] = t2; g_wn2e[k] = t2 * 1.44269504f; }
}

// ---------------- prep: normalize inputs (NHWC gather) ----------------
__global__ void prep_x(const float* __restrict__ in) {
    int warp = threadIdx.x >> 5, lane = threadIdx.x & 31;
    int n = blockIdx.x * 8 + warp;
    int b = n >> 10, h = (n >> 5) & 31, w = n & 31;
    const float* base = in + (size_t)b * 262144 + h * 32 + w;
    float v[8];
#pragma unroll
    for (int j = 0; j < 8; j++) v[j] = base[(size_t)(lane + 32 * j) * 1024];
    float s = 0.f;
#pragma unroll
    for (int j = 0; j < 8; j++) s = fmaf(v[j], v[j], s);
#pragma unroll
    for (int o = 16; o; o >>= 1) s += __shfl_xor_sync(0xffffffffu, s, o);
    float den = fmaxf(sqrtf(s), 1e-12f);
    float t2 = 0.f;
#pragma unroll
    for (int j = 0; j < 8; j++) {
        float fn = v[j] / den;
        g_fn[(size_t)n * CDIM + lane + 32 * j] = fn;
        t2 = fmaf(fn, fn, t2);
    }
#pragma unroll
    for (int o = 16; o; o >>= 1) t2 += __shfl_xor_sync(0xffffffffu, t2, o);
    if (lane == 0) g_fn2e[n] = t2 * 1.44269504f;
}

__global__ void zero_counts() {
    int t = blockIdx.x * 256 + threadIdx.x;
    if (t < KEMB) g_counts[t] = 0;
}

// ---------------- B tile fill: 32 codewords x 256 dims, hi+lo, padded rows -------------
__device__ __forceinline__ void load_btile(__nv_bfloat16* ring, int buf, int tile, int tid) {
    __nv_bfloat16* base = ring + (size_t)buf * BUF_ELEMS;
#pragma unroll
    for (int j = 0; j < 8; j++) {
        int q = tid + 256 * j;          // 0..2047 16B chunks
        int isLo = q >> 10;
        int qq = q & 1023;
        int r = qq >> 5;                // codeword row 0..31
        int c = qq & 31;                // 16B chunk in row (8 bf16)
        __nv_bfloat16* dst = base + isLo * (32 * BPAD) + r * BPAD + c * 8;
        const __nv_bfloat16* src = (isLo ? g_wlk : g_whk) + (size_t)(tile * 32 + r) * CDIM + c * 8;
        cpa16_s(dst, src);
    }
}

// ---------------- main: HMMA (mma.sync bf16 hi/lo) + fused exp / top-2 / rowsum --------
// CTA: 128 tokens, 8 warps; warp owns 16 rows. A fragments in registers (hi+lo).
// B: 4-deep cp.async ring of 32-col tiles. Epilogue fused per tile.
__global__ __launch_bounds__(256, 1) void vq_mma(float* __restrict__ out) {
    extern __shared__ __align__(16) char dsm[];
    __nv_bfloat16* ring = (__nv_bfloat16*)dsm;

    const int tid = threadIdx.x;
    const int wid = tid >> 5, lane = tid & 31;
    const int g = lane >> 2, q = lane & 3;
    const int row0 = blockIdx.x * 128;
    const int rowA = row0 + wid * 16 + g;        // this thread's first row; second = +8

    // ---- A fragments: load fp32, split to bf16 hi/lo, keep in registers ----
    uint32_t ahi[16][4], alo[16][4];
    {
        const float* fr0 = g_fn + (size_t)rowA * CDIM;
        const float* fr1 = fr0 + 8 * CDIM;
#pragma unroll
        for (int k = 0; k < 16; k++) {
            int c0 = k * 16 + q * 2;
            float2 x00 = *(const float2*)(fr0 + c0);
            float2 x10 = *(const float2*)(fr1 + c0);
            float2 x01 = *(const float2*)(fr0 + c0 + 8);
            float2 x11 = *(const float2*)(fr1 + c0 + 8);
            packhl(x00.x, x00.y, ahi[k][0], alo[k][0]);
            packhl(x10.x, x10.y, ahi[k][1], alo[k][1]);
            packhl(x01.x, x01.y, ahi[k][2], alo[k][2]);
            packhl(x11.x, x11.y, ahi[k][3], alo[k][3]);
        }
    }
    const float a2e0 = g_fn2e[rowA];
    const float a2e1 = g_fn2e[rowA + 8];

    float rsum[2] = {0.f, 0.f};
    float rm1[2] = {3.4e38f, 3.4e38f}, rm2[2] = {3.4e38f, 3.4e38f};
    int ri1[2] = {0x7fffffff, 0x7fffffff}, ri2[2] = {0x7fffffff, 0x7fffffff};

    float* soft = out + SOFT_OFF;

    // prologue: tiles 0..2 in flight
    load_btile(ring, 0, 0, tid); asm volatile("cp.async.commit_group;");
    load_btile(ring, 1, 1, tid); asm volatile("cp.async.commit_group;");
    load_btile(ring, 2, 2, tid); asm volatile("cp.async.commit_group;");

    for (int t = 0; t < NT; ++t) {
        if (t + 3 < NT) {
            load_btile(ring, (t + 3) & 3, t + 3, tid);
            asm volatile("cp.async.commit_group;");
            asm volatile("cp.async.wait_group 3;");
        } else {
            int r = NT - 1 - t;
            if (r == 2)      asm volatile("cp.async.wait_group 2;");
            else if (r == 1) asm volatile("cp.async.wait_group 1;");
            else             asm volatile("cp.async.wait_group 0;");
        }
        __syncthreads();                       // B[t] visible

        const __nv_bfloat16* Bt = ring + (size_t)(t & 3) * BUF_ELEMS;
        float acc[4][4];
#pragma unroll
        for (int n = 0; n < 4; n++)
#pragma unroll
            for (int j = 0; j < 4; j++) acc[n][j] = 0.f;

#pragma unroll
        for (int k = 0; k < 16; k++) {
            int kb = k * 16 + q * 2;
#pragma unroll
            for (int n = 0; n < 4; n++) {
                const __nv_bfloat16* bh = Bt + (n * 8 + g) * BPAD + kb;
                const __nv_bfloat16* bl = bh + 32 * BPAD;
                uint32_t bhi[2], blo[2];
                bhi[0] = *(const uint32_t*)bh;
                bhi[1] = *(const uint32_t*)(bh + 8);
                blo[0] = *(const uint32_t*)bl;
                blo[1] = *(const uint32_t*)(bl + 8);
                mma_bf16(acc[n], ahi[k], bhi);
                mma_bf16(acc[n], alo[k], bhi);
                mma_bf16(acc[n], ahi[k], blo);
            }
        }

        // fused epilogue for tile t (cols t*32 .. +31)
        const int cb = t * 32;
#pragma unroll
        for (int n = 0; n < 4; n++) {
            int c0 = cb + n * 8 + q * 2;
            float w2a = g_wn2[c0], w2b = g_wn2[c0 + 1];
            float wea = g_wn2e[c0], web = g_wn2e[c0 + 1];
            // row rowA (acc c0,c1)  /  row rowA+8 (acc c2,c3)
#pragma unroll
            for (int s = 0; s < 2; s++) {
                float d0 = acc[n][s * 2 + 0], d1 = acc[n][s * 2 + 1];
                float a2 = s ? a2e1 : a2e0;
                float m0 = fmaf(d0, -2.0f, w2a);
                float m1v = fmaf(d1, -2.0f, w2b);
                if (m0 < rm2[s]) {
                    if (m0 < rm1[s]) { rm2[s] = rm1[s]; ri2[s] = ri1[s]; rm1[s] = m0; ri1[s] = c0; }
                    else             { rm2[s] = m0; ri2[s] = c0; }
                }
                if (m1v < rm2[s]) {
                    if (m1v < rm1[s]) { rm2[s] = rm1[s]; ri2[s] = ri1[s]; rm1[s] = m1v; ri1[s] = c0 + 1; }
                    else              { rm2[s] = m1v; ri2[s] = c0 + 1; }
                }
                float t0 = fmaf(d0, 2.88539008f, -(a2 + wea));
                float t1 = fmaf(d1, 2.88539008f, -(a2 + web));
                float e0, e1;
                asm("ex2.approx.f32 %0, %1;" : "=f"(e0) : "f"(t0));
                asm("ex2.approx.f32 %0, %1;" : "=f"(e1) : "f"(t1));
                rsum[s] += e0 + e1;
                *(float2*)(soft + (size_t)(rowA + s * 8) * KEMB + c0) = make_float2(e0, e1);
            }
        }
        __syncthreads();                       // all reads of B[t] done before ring reuse
    }

    // ---- CTA reduction: rowsum Z + top-4 candidates (deterministic) ----
    float* rs = (float*)dsm;                   // [128][4]
    float* m1a = rs + 512;                     // [128][4]
    float* m2a = m1a + 512;
    int*   i1a = (int*)(m2a + 512);
    int*   i2a = i1a + 512;
    __syncthreads();
#pragma unroll
    for (int s = 0; s < 2; s++) {
        int rl = wid * 16 + g + s * 8;
        rs[rl * 4 + q]  = rsum[s];
        m1a[rl * 4 + q] = rm1[s];
        m2a[rl * 4 + q] = rm2[s];
        i1a[rl * 4 + q] = ri1[s];
        i2a[rl * 4 + q] = ri2[s];
    }
    __syncthreads();
    if (tid < 128) {
        int r = tid;
        float sum = rs[r * 4] + rs[r * 4 + 1] + rs[r * 4 + 2] + rs[r * 4 + 3];
        g_Z[row0 + r] = sum;
        float bm[4]; int bi[4];
#pragma unroll
        for (int j = 0; j < 4; j++) { bm[j] = 3.4e38f; bi[j] = 0x7fffffff; }
        for (int u = 0; u < 8; u++) {
            float m = (u & 1) ? m2a[r * 4 + (u >> 1)] : m1a[r * 4 + (u >> 1)];
            int  iv = (u & 1) ? i2a[r * 4 + (u >> 1)] : i1a[r * 4 + (u >> 1)];
            if (m < bm[3] || (m == bm[3] && iv < bi[3])) {
                int j = 3;
                while (j > 0 && (m < bm[j - 1] || (m == bm[j - 1] && iv < bi[j - 1]))) {
                    bm[j] = bm[j - 1]; bi[j] = bi[j - 1]; --j;
                }
                bm[j] = m; bi[j] = iv;
            }
        }
#pragma unroll
        for (int j = 0; j < 4; j++) g_cand[row0 + r][j] = bi[j];
    }
}

// ---------------- argmin refine: exact (double) over 4 candidates ----------------
__global__ void refine_k() {
    int warp = threadIdx.x >> 5, lane = threadIdx.x & 31;
    int n = blockIdx.x * 8 + warp;
    int cand = lane >> 3, part = lane & 7;
    int k = g_cand[n][cand];
    const float* fnr = g_fn + (size_t)n * CDIM;
    const float* wr  = g_wn + (size_t)k * CDIM;
    double dot = 0.0, w2 = 0.0;
    int c0 = part * 32;
#pragma unroll 8
    for (int c = c0; c < c0 + 32; c++) {
        double w = (double)wr[c];
        dot = fma((double)fnr[c], w, dot);
        w2  = fma(w, w, w2);
    }
#pragma unroll
    for (int o = 1; o < 8; o <<= 1) {
        dot += __shfl_xor_sync(0xffffffffu, dot, o);
        w2  += __shfl_xor_sync(0xffffffffu, w2,  o);
    }
    double d = w2 - 2.0 * dot;
#pragma unroll
    for (int o = 8; o < 32; o <<= 1) {
        double od = __shfl_xor_sync(0xffffffffu, d, o);
        int    ok = __shfl_xor_sync(0xffffffffu, k, o);
        if (od < d || (od == d && ok < k)) { d = od; k = ok; }
    }
    if (lane == 0) g_idx[n] = k;
}

// ---------------- scale soft codes by 1/Z ----------------
__global__ void scale_soft(float* __restrict__ out) {
    float2* soft = (float2*)(out + SOFT_OFF);
    size_t base = (size_t)blockIdx.x * 256 + threadIdx.x;
#pragma unroll
    for (int qq = 0; qq < 4; qq++) {
        size_t i = base + (size_t)qq * 16777216u;
        int n = (int)(i >> 12);
        float inv = 1.0f / g_Z[n];
        float2 v = soft[i];
        v.x *= inv; v.y *= inv;
        soft[i] = v;
    }
}

// ---------------- gather quantized, loss partials, counts, indices ----------------
__global__ void quantize_k(const float* __restrict__ in, const float* __restrict__ emb,
                           float* __restrict__ out) {
    int warp = threadIdx.x >> 5, lane = threadIdx.x & 31;
    int n = blockIdx.x * 8 + warp;
    int idx = g_idx[n];
    int b = n >> 10, h = (n >> 5) & 31, w = n & 31;
    const float* er = emb + (size_t)idx * CDIM;
    const float* xb = in + (size_t)b * 262144 + h * 32 + w;
    float* ob = out + (size_t)b * 262144 + w * 32 + h;   // [B,C,W,H]
    float ls = 0.f;
#pragma unroll
    for (int j = 0; j < 8; j++) {
        int c = lane + 32 * j;
        float qv = er[c];
        float x = xb[(size_t)c * 1024];
        float d = qv - x;
        ls = fmaf(d, d, ls);
        ob[(size_t)c * 1024] = qv;
    }
#pragma unroll
    for (int o = 16; o; o >>= 1) ls += __shfl_xor_sync(0xffffffffu, ls, o);
    if (lane == 0) {
        g_losspart[n] = ls;
        atomicAdd(&g_counts[idx], 1);
        out[IDX_OFF + n] = (float)idx;
    }
}

// ---------------- final scalars ----------------
__global__ void finalize_k(float* __restrict__ out) {
    __shared__ float sred[1024];
    int tid = threadIdx.x;
    float s = 0.f;
    for (int i = 0; i < 16; i++) s += g_losspart[tid + 1024 * i];
    sred[tid] = s; __syncthreads();
    for (int o = 512; o; o >>= 1) { if (tid < o) sred[tid] += sred[tid + o]; __syncthreads(); }
    if (tid == 0) out[LOSS_OFF] = 0.25f * (sred[0] * (1.0f / 4194304.0f));
    __syncthreads();
    float e = 0.f;
    for (int i = 0; i < 8; i++) {
        float p = (float)g_counts[tid + 1024 * i] * (1.0f / 16384.0f);
        e += p * logf(p + 1e-10f);
    }
    sred[tid] = e; __syncthreads();
    for (int o = 512; o; o >>= 1) { if (tid < o) sred[tid] += sred[tid + o]; __syncthreads(); }
    if (tid == 0) out[PERP_OFF] = expf(-sred[0]);
}

// ---------------- launcher ----------------
extern "C" void kernel_launch(void* const* d_in, const int* in_sizes, int n_in,
                              void* d_out, int out_size) {
    (void)in_sizes; (void)n_in; (void)out_size;
    const float* in  = (const float*)d_in[0];
    const float* emb = (const float*)d_in[1];
    float* out = (float*)d_out;

    const int dyn = 4 * BUF_ELEMS * 2;   // 4 ring buffers (bytes) = 135168
    cudaFuncSetAttribute(vq_mma, cudaFuncAttributeMaxDynamicSharedMemorySize, dyn);

    prep_w<<<KEMB / 8, 256>>>(emb);
    prep_x<<<NTOK / 8, 256>>>(in);
    zero_counts<<<32, 256>>>();
    vq_mma<<<NTOK / 128, 256, dyn>>>(out);
    refine_k<<<NTOK / 8, 256>>>();
    scale_soft<<<65536, 256>>>(out);
    quantize_k<<<NTOK / 8, 256>>>(in, emb, out);
    finalize_k<<<1, 1024>>>(out);
}